// round 14
// baseline (speedup 1.0000x reference)
#include <cuda_runtime.h>
#include <cuda_bf16.h>
#include <cstdint>

// ---------------------------------------------------------------------------
// GNN: 2-layer GraphSAGE (mean aggr) + global mean pool.
// GEMMs: mma.sync m16n8k16 bf16 (HMMA), split-bf16 3-term (AhBh+AhBl+AlBh).
// A operand: interleaved {hi,lo} pairs (uint32/elem), PRMT-split in regs.
// B (weights): pre-permuted hi/lo bf16x2 PLANES in global -> B fragment is a
// single LDS.64 per plane, zero PRMT on the B path (-32 PRMT per warp-k16).
// ROWB=24 (96B) plane rows: half-warp LDS.64 bases {0,24,16,8} mod 32 ->
// conflict-free. Everything else byte-identical to the 252us round-13 build.
// ---------------------------------------------------------------------------

#define MAXN 100000
#define MAXE 600000
#define NG   64
#define DD   128

// Scratch (device globals -- no runtime allocation allowed)
__device__ uint32_t g_xp  [MAXN * DD];   // x as pairs
__device__ uint32_t g_aggp[MAXN * DD];   // aggregation output as pairs
__device__ uint32_t g_h1p [MAXN * DD];   // h1 (post-relu) as pairs
__device__ uint32_t g_w1h[128 * 128], g_w1l[128 * 128];  // permuted planes
__device__ uint32_t g_w2h[128 * 128], g_w2l[128 * 128];  // [nn][kword], K=256
__device__ int      g_cnt[MAXN];         // invariant: all-zero at entry
__device__ int      g_rowptr[MAXN + 1];
__device__ int      g_cursor[MAXN];
__device__ int      g_col[MAXE];
__device__ float    g_gsum[NG * DD];     // invariant: all-zero at entry
__device__ float    g_gcnt[NG];          // invariant: all-zero at entry
__device__ int      g_bsums[1024];

// ------------------------------------------------------------- bf16 pair ops
__device__ __forceinline__ uint32_t f2pair(float f) {
    __nv_bfloat16 h = __float2bfloat16(f);
    float hf = __bfloat162float(h);
    __nv_bfloat16 l = __float2bfloat16(f - hf);
    return (uint32_t)__bfloat16_as_ushort(h) |
           ((uint32_t)__bfloat16_as_ushort(l) << 16);
}
__device__ __forceinline__ float pair2f(uint32_t p) {
    float h = __uint_as_float(p << 16);
    float l = __uint_as_float(p & 0xffff0000u);
    return h + l;
}
// {hi(a),hi(b)} and {lo(a),lo(b)} bf16x2 words (a in low half)
__device__ __forceinline__ uint2 split2(float a, float b) {
    __nv_bfloat16 ah = __float2bfloat16(a), bh = __float2bfloat16(b);
    float ar = a - __bfloat162float(ah);
    float br = b - __bfloat162float(bh);
    __nv_bfloat16 al = __float2bfloat16(ar), bl = __float2bfloat16(br);
    uint2 r;
    r.x = (uint32_t)__bfloat16_as_ushort(ah) |
          ((uint32_t)__bfloat16_as_ushort(bh) << 16);
    r.y = (uint32_t)__bfloat16_as_ushort(al) |
          ((uint32_t)__bfloat16_as_ushort(bl) << 16);
    return r;
}
__device__ __forceinline__ uint32_t prmt(uint32_t a, uint32_t b, uint32_t s) {
    uint32_t r;
    asm("prmt.b32 %0,%1,%2,%3;" : "=r"(r) : "r"(a), "r"(b), "r"(s));
    return r;
}

// --------------------------------------------------------------- PTX helpers
__device__ __forceinline__ uint32_t smem_u32(const void* p) {
    uint32_t a;
    asm("{ .reg .u64 t; cvta.to.shared.u64 t, %1; cvt.u32.u64 %0, t; }"
        : "=r"(a) : "l"(p));
    return a;
}
__device__ __forceinline__ void cpasync16(uint32_t smem, const void* gmem, int sz) {
    asm volatile("cp.async.ca.shared.global [%0], [%1], 16, %2;"
                 :: "r"(smem), "l"(gmem), "r"(sz));
}
__device__ __forceinline__ void cp_commit() {
    asm volatile("cp.async.commit_group;");
}
__device__ __forceinline__ void cp_wait1() {
    asm volatile("cp.async.wait_group 1;");
}
__device__ __forceinline__ void cp_wait0() {
    asm volatile("cp.async.wait_group 0;");
}

// mma.sync m16n8k16, bf16 x bf16 -> f32, accumulate in place
__device__ __forceinline__ void mma_bf16(float (&c)[4],
                                         uint32_t a0, uint32_t a1,
                                         uint32_t a2, uint32_t a3,
                                         uint32_t b0, uint32_t b1) {
    asm volatile(
        "mma.sync.aligned.m16n8k16.row.col.f32.bf16.bf16.f32 "
        "{%0,%1,%2,%3}, {%4,%5,%6,%7}, {%8,%9}, {%0,%1,%2,%3};"
        : "+f"(c[0]), "+f"(c[1]), "+f"(c[2]), "+f"(c[3])
        : "r"(a0), "r"(a1), "r"(a2), "r"(a3), "r"(b0), "r"(b1));
}

// ----------------- degree counts + x->pairs + weights->planes (merged, indep)
__global__ void k_cntcvt(const int* __restrict__ dst, int e,
                         const float2* __restrict__ x2,
                         const float* __restrict__ W1l, const float* __restrict__ W1r,
                         const float* __restrict__ W2l, const float* __restrict__ W2r,
                         int n) {
    int i = blockIdx.x * blockDim.x + threadIdx.x;
    if (i < e) atomicAdd(&g_cnt[dst[i]], 1);
    int nx = n * 64;                      // float2 units of x
    if (i < nx) {
        float2 v = x2[i];
        uint2 o;
        o.x = f2pair(v.x);
        o.y = f2pair(v.y);
        *(uint2*)&g_xp[2 * i] = o;
    } else {
        int j = i - nx;
        if (j >= 2 * 128 * 128) return;   // 2 layers x 128 cols x 128 kwords
        int which = j >> 14;
        int idx = j & 16383;
        int nn = idx >> 7;                // output col 0..127
        int jw = idx & 127;               // plane word (elements 2jw, 2jw+1)
        int k0 = jw * 2;
        float a, b;
        if (which == 0) {
            if (k0 < 128) { a = W1l[k0 * 128 + nn]; b = W1l[(k0 + 1) * 128 + nn]; }
            else { a = W1r[(k0 - 128) * 128 + nn]; b = W1r[(k0 - 127) * 128 + nn]; }
        } else {
            if (k0 < 128) { a = W2l[k0 * 128 + nn]; b = W2l[(k0 + 1) * 128 + nn]; }
            else { a = W2r[(k0 - 128) * 128 + nn]; b = W2r[(k0 - 127) * 128 + nn]; }
        }
        uint2 p = split2(a, b);
        // fragment permutation within each 8-word group:
        // orig offset o -> pos 2o (o<4) else 2(o-4)+1, so LDS.64 at 2t = (b0,b1)
        int o = jw & 7;
        int pos = (o < 4) ? (2 * o) : (2 * (o - 4) + 1);
        int widx = nn * 128 + (jw & ~7) + pos;
        if (which == 0) { g_w1h[widx] = p.x; g_w1l[widx] = p.y; }
        else            { g_w2h[widx] = p.x; g_w2l[widx] = p.y; }
    }
}

// ---------------------------------------------- scan level 1 (per 1024 block)
__global__ void k_scan1(int n) {
    __shared__ int s[1024];
    int t = threadIdx.x;
    int i = blockIdx.x * 1024 + t;
    int v = (i < n) ? g_cnt[i] : 0;
    s[t] = v;
    __syncthreads();
    #pragma unroll
    for (int off = 1; off < 1024; off <<= 1) {
        int u = (t >= off) ? s[t - off] : 0;
        __syncthreads();
        s[t] += u;
        __syncthreads();
    }
    if (i < n) g_rowptr[i] = s[t];              // inclusive within block
    if (t == 1023) g_bsums[blockIdx.x] = s[1023];
}

// ------------- scan finalize: per-block smem prefix of bsums (folds scan2)
__global__ void k_scan3(int n, int e, int nb) {
    __shared__ int s[128];                      // nb <= 98 for MAXN=100000
    int t = threadIdx.x;
    if (t == 0) {
        int run = 0;
        for (int b = 0; b < nb; b++) { int v = g_bsums[b]; s[b] = run; run += v; }
    }
    __syncthreads();
    int i = blockIdx.x * blockDim.x + t;
    if (i < n) {
        int ex = s[i >> 10] + g_rowptr[i] - g_cnt[i];
        g_rowptr[i] = ex;
        g_cursor[i] = ex;
    }
    if (i == 0) g_rowptr[n] = e;
}

// ------------------------- CSR bucket fill (+ restore g_cnt zero-invariant)
__global__ void k_fill(const int* __restrict__ src, const int* __restrict__ dst,
                       int e, int n) {
    int i = blockIdx.x * blockDim.x + threadIdx.x;
    if (i < e) {
        int d = dst[i];
        int p = atomicAdd(&g_cursor[d], 1);
        g_col[p] = src[i];
    }
    if (i < n) g_cnt[i] = 0;
}

// -------------------------------------- mean aggregation, fp32 input (layer 1)
__global__ void k_agg_f(const float4* __restrict__ xin, uint32_t* __restrict__ outp, int n) {
    int gt = blockIdx.x * blockDim.x + threadIdx.x;
    int node = gt >> 5;
    int lane = gt & 31;
    if (node >= n) return;
    int beg = g_rowptr[node];
    int end = g_rowptr[node + 1];
    float4 acc = make_float4(0.f, 0.f, 0.f, 0.f);
    for (int e = beg; e < end; e++) {
        int j = g_col[e];
        float4 v = __ldg(&xin[j * 32 + lane]);
        acc.x += v.x; acc.y += v.y; acc.z += v.z; acc.w += v.w;
    }
    int deg = end - beg;
    float s = 1.0f / (float)(deg > 0 ? deg : 1);
    uint4 o;
    o.x = f2pair(acc.x * s); o.y = f2pair(acc.y * s);
    o.z = f2pair(acc.z * s); o.w = f2pair(acc.w * s);
    *(uint4*)&outp[node * 128 + lane * 4] = o;
}

// -------------------------------------- mean aggregation, pair input (layer 2)
__global__ void k_agg_p(const uint4* __restrict__ inp, uint32_t* __restrict__ outp, int n) {
    int gt = blockIdx.x * blockDim.x + threadIdx.x;
    int node = gt >> 5;
    int lane = gt & 31;
    if (node >= n) return;
    int beg = g_rowptr[node];
    int end = g_rowptr[node + 1];
    float4 acc = make_float4(0.f, 0.f, 0.f, 0.f);
    for (int e = beg; e < end; e++) {
        int j = g_col[e];
        uint4 v = __ldg(&inp[j * 32 + lane]);
        acc.x += pair2f(v.x); acc.y += pair2f(v.y);
        acc.z += pair2f(v.z); acc.w += pair2f(v.w);
    }
    int deg = end - beg;
    float s = 1.0f / (float)(deg > 0 ? deg : 1);
    uint4 o;
    o.x = f2pair(acc.x * s); o.y = f2pair(acc.y * s);
    o.z = f2pair(acc.z * s); o.w = f2pair(acc.w * s);
    *(uint4*)&outp[node * 128 + lane * 4] = o;
}

// ------------------------------------------------- split-bf16 HMMA dual GEMM
// C[M=128/blk, N=128] = [A0 | A1](K=256 pairs) @ W^T + bias (3 MMA terms).
// A smem: 160B rows (conflict-free). B smem: hi/lo plane tiles, 96B rows
// (half-warp bases {0,24,16,8} mod 32 -> conflict-free); permuted global
// layout makes each B fragment one LDS.64 per plane, zero PRMT.
#define ROWA 40                                  // uint32 per A smem row
#define ROWB 24                                  // uint32 per B plane smem row
#define A_BYTES (128 * ROWA * 4)                 // 20480
#define BPL_BYTES (128 * ROWB * 4)               // 12288
#define STAGE_BYTES (A_BYTES + 2 * BPL_BYTES)    // 45056
#define TILE_STRIDE 132                          // fp32 pool-tile row stride

template <bool RELU, bool PAIR_OUT, bool POOL>
__global__ void __launch_bounds__(256, 2)
k_gemm_mma(const uint32_t* __restrict__ A0, const uint32_t* __restrict__ A1,
           const uint32_t* __restrict__ BhG, const uint32_t* __restrict__ BlG,
           const float* __restrict__ bias,
           void* __restrict__ Cout, const int* __restrict__ batch, int n) {
    extern __shared__ __align__(16) unsigned char smraw[];
    uint32_t sbase = smem_u32(smraw);

    int tid = threadIdx.x;
    int wid = tid >> 5;
    int lid = tid & 31;
    int g = lid >> 2;                 // group 0..7
    int t = lid & 3;                  // thread-in-group
    int rowBase = blockIdx.x * 128;
    int rowWarp = (wid >> 1) * 32;    // warp tile: 32 rows x 64 cols
    int colWarp = (wid & 1) * 64;

    float acc[2][8][4];
    #pragma unroll
    for (int rt = 0; rt < 2; rt++)
        #pragma unroll
        for (int ct = 0; ct < 8; ct++)
            #pragma unroll
            for (int q = 0; q < 4; q++) acc[rt][ct][q] = 0.0f;

    // ---- chunk loader (k-chunk c -> stage st) -------------------------------
    auto load_chunk = [&](int c, int st) {
        const uint32_t* Asrc = (c < 4) ? A0 : A1;
        int ko = (c & 3) * 32;            // pair offset within A source row
        int kb = c * 16;                  // plane-word offset within B row
        uint32_t sA  = sbase + st * STAGE_BYTES;
        uint32_t sBh = sA + A_BYTES;
        uint32_t sBl = sBh + BPL_BYTES;
        #pragma unroll
        for (int j = 0; j < 4; j++) {     // A: 128 rows x 32 pairs = 1024 x16B
            int idx = tid + j * 256;
            int r = idx >> 3, seg = idx & 7;
            int gr = rowBase + r;
            int sz = (gr < n) ? 16 : 0;
            int grc = (gr < n) ? gr : (n - 1);
            cpasync16(sA + r * (ROWA * 4) + seg * 16,
                      Asrc + (size_t)grc * 128 + ko + seg * 4, sz);
        }
        #pragma unroll
        for (int j = 0; j < 4; j++) {     // Bh+Bl: 128 rows x 4 x16B each
            int idx = tid + j * 256;
            int r = idx >> 3, s = idx & 7;
            if (s < 4)
                cpasync16(sBh + r * (ROWB * 4) + s * 16,
                          BhG + r * 128 + kb + s * 4, 16);
            else
                cpasync16(sBl + r * (ROWB * 4) + (s - 4) * 16,
                          BlG + r * 128 + kb + (s - 4) * 4, 16);
        }
        cp_commit();
    };

    load_chunk(0, 0);

    for (int c = 0; c < 8; c++) {
        if (c < 7) { load_chunk(c + 1, (c + 1) & 1); cp_wait1(); }
        else       { cp_wait0(); }
        __syncthreads();

        const uint32_t* sA  = (const uint32_t*)(smraw + (c & 1) * STAGE_BYTES);
        const uint32_t* sBh = sA + 128 * ROWA;
        const uint32_t* sBl = sBh + 128 * ROWB;

        #pragma unroll
        for (int kk2 = 0; kk2 < 2; kk2++) {
            int kk = kk2 * 16;
            uint32_t Ah[2][4], Al[2][4];
            #pragma unroll
            for (int rt = 0; rt < 2; rt++) {
                const uint32_t* p0 = sA + (rowWarp + rt * 16 + g) * ROWA + kk + 2 * t;
                const uint32_t* p1 = p0 + 8 * ROWA;
                uint2 q;
                q = *(const uint2*)p0;
                Ah[rt][0] = prmt(q.x, q.y, 0x5410); Al[rt][0] = prmt(q.x, q.y, 0x7632);
                q = *(const uint2*)p1;
                Ah[rt][1] = prmt(q.x, q.y, 0x5410); Al[rt][1] = prmt(q.x, q.y, 0x7632);
                q = *(const uint2*)(p0 + 8);
                Ah[rt][2] = prmt(q.x, q.y, 0x5410); Al[rt][2] = prmt(q.x, q.y, 0x7632);
                q = *(const uint2*)(p1 + 8);
                Ah[rt][3] = prmt(q.x, q.y, 0x5410); Al[rt][3] = prmt(q.x, q.y, 0x7632);
            }
            #pragma unroll
            for (int ct = 0; ct < 8; ct++) {
                int boff = (colWarp + ct * 8 + g) * ROWB + kk2 * 8 + 2 * t;
                uint2 qh = *(const uint2*)(sBh + boff);   // (Bh0, Bh1)
                uint2 ql = *(const uint2*)(sBl + boff);   // (Bl0, Bl1)
                #pragma unroll
                for (int rt = 0; rt < 2; rt++) {
                    mma_bf16(acc[rt][ct], Ah[rt][0], Ah[rt][1], Ah[rt][2], Ah[rt][3], qh.x, qh.y);
                    mma_bf16(acc[rt][ct], Ah[rt][0], Ah[rt][1], Ah[rt][2], Ah[rt][3], ql.x, ql.y);
                    mma_bf16(acc[rt][ct], Al[rt][0], Al[rt][1], Al[rt][2], Al[rt][3], qh.x, qh.y);
                }
            }
        }
        __syncthreads();
    }

    // ---- epilogue -----------------------------------------------------------
    float bc0[8], bc1[8];
    #pragma unroll
    for (int ct = 0; ct < 8; ct++) {
        int col = colWarp + ct * 8 + 2 * t;
        bc0[ct] = __ldg(&bias[col]);
        bc1[ct] = __ldg(&bias[col + 1]);
    }

    if (POOL) {
        // Fused global-mean-pool: stash tile in smem (stage buffers are dead
        // after the last __syncthreads), segment-sum columns by sorted batch.
        float* tile = (float*)smraw;                          // 128 x TILE_STRIDE
        int* sbatch = (int*)(smraw + 128 * TILE_STRIDE * 4);  // 128 ids
        #pragma unroll
        for (int rt = 0; rt < 2; rt++) {
            #pragma unroll
            for (int half = 0; half < 2; half++) {
                int lrow = rowWarp + rt * 16 + half * 8 + g;
                #pragma unroll
                for (int ct = 0; ct < 8; ct++) {
                    int col = colWarp + ct * 8 + 2 * t;
                    float v0 = acc[rt][ct][half * 2 + 0] + bc0[ct];
                    float v1 = acc[rt][ct][half * 2 + 1] + bc1[ct];
                    if (RELU) { v0 = fmaxf(v0, 0.f); v1 = fmaxf(v1, 0.f); }
                    float2 o; o.x = v0; o.y = v1;
                    *(float2*)&tile[lrow * TILE_STRIDE + col] = o;
                }
            }
        }
        if (tid < 128) {
            int gr = rowBase + tid;
            sbatch[tid] = (gr < n) ? __ldg(&batch[gr]) : -1;
        }
        __syncthreads();
        if (tid < 128) {
            int col = tid;
            float pacc = 0.0f;
            int cur = sbatch[0];
            int cnt = 0;
            for (int r = 0; r < 128; r++) {
                int b = sbatch[r];
                if (b != cur) {
                    if (cur >= 0) {
                        atomicAdd(&g_gsum[cur * DD + col], pacc);
                        if (col == 0) atomicAdd(&g_gcnt[cur], (float)cnt);
                    }
                    pacc = 0.0f; cnt = 0; cur = b;
                }
                if (b >= 0) { pacc += tile[r * TILE_STRIDE + col]; cnt++; }
            }
            if (cur >= 0) {
                atomicAdd(&g_gsum[cur * DD + col], pacc);
                if (col == 0) atomicAdd(&g_gcnt[cur], (float)cnt);
            }
        }
    } else {
        #pragma unroll
        for (int rt = 0; rt < 2; rt++) {
            #pragma unroll
            for (int half = 0; half < 2; half++) {
                int grow = rowBase + rowWarp + rt * 16 + half * 8 + g;
                if (grow >= n) continue;
                #pragma unroll
                for (int ct = 0; ct < 8; ct++) {
                    int col = colWarp + ct * 8 + 2 * t;
                    float v0 = acc[rt][ct][half * 2 + 0] + bc0[ct];
                    float v1 = acc[rt][ct][half * 2 + 1] + bc1[ct];
                    if (RELU) { v0 = fmaxf(v0, 0.f); v1 = fmaxf(v1, 0.f); }
                    if (PAIR_OUT) {
                        uint2 o; o.x = f2pair(v0); o.y = f2pair(v1);
                        *(uint2*)&((uint32_t*)Cout)[(size_t)grow * 128 + col] = o;
                    } else {
                        float2 o; o.x = v0; o.y = v1;
                        *(float2*)&((float*)Cout)[(size_t)grow * 128 + col] = o;
                    }
                }
            }
        }
    }
}

// -------------- final output (single block; restores zero-invariants)
__global__ void k_final(float* __restrict__ out) {
    __shared__ float sc[NG];
    int t = threadIdx.x;
    if (t < NG) sc[t] = g_gcnt[t];
    __syncthreads();
    for (int i = t; i < NG * DD; i += 1024) {
        out[i] = g_gsum[i] / fmaxf(sc[i >> 7], 1.0f);
        g_gsum[i] = 0.0f;
    }
    if (t < NG) g_gcnt[t] = 0.0f;
}

// ---------------------------------------------------------------------------
extern "C" void kernel_launch(void* const* d_in, const int* in_sizes, int n_in,
                              void* d_out, int out_size) {
    (void)n_in; (void)out_size;
    const float* x     = (const float*)d_in[0];
    const int*   ei    = (const int*)  d_in[1];
    const int*   batch = (const int*)  d_in[2];
    const float* W1l   = (const float*)d_in[3];
    const float* b1    = (const float*)d_in[4];
    const float* W1r   = (const float*)d_in[5];
    const float* W2l   = (const float*)d_in[6];
    const float* b2    = (const float*)d_in[7];
    const float* W2r   = (const float*)d_in[8];
    float*       out   = (float*)d_out;

    int n = in_sizes[0] / 128;   // nodes
    int e = in_sizes[1] / 2;     // edges
    const int* src = ei;         // edge_index[0]
    const int* dst = ei + e;     // edge_index[1]

    void *p_xp, *p_aggp, *p_h1p, *pw1h, *pw1l, *pw2h, *pw2l;
    cudaGetSymbolAddress(&p_xp,   g_xp);
    cudaGetSymbolAddress(&p_aggp, g_aggp);
    cudaGetSymbolAddress(&p_h1p,  g_h1p);
    cudaGetSymbolAddress(&pw1h,   g_w1h);
    cudaGetSymbolAddress(&pw1l,   g_w1l);
    cudaGetSymbolAddress(&pw2h,   g_w2h);
    cudaGetSymbolAddress(&pw2l,   g_w2l);
    uint32_t* xp   = (uint32_t*)p_xp;
    uint32_t* aggp = (uint32_t*)p_aggp;
    uint32_t* h1p  = (uint32_t*)p_h1p;

    const int GEMM_SMEM = 2 * STAGE_BYTES;   // 90112 (covers pool tile 68096)
    cudaFuncSetAttribute(k_gemm_mma<true, true, false>,
                         cudaFuncAttributeMaxDynamicSharedMemorySize, GEMM_SMEM);
    cudaFuncSetAttribute(k_gemm_mma<false, false, true>,
                         cudaFuncAttributeMaxDynamicSharedMemorySize, GEMM_SMEM);

    int nb = (n + 1023) / 1024;

    // Counts + conversions in one kernel (g_cnt arrives zeroed)
    int cvtTot = n * 64 + 2 * 128 * 128;
    int cntTot = (cvtTot > e) ? cvtTot : e;
    k_cntcvt<<<(cntTot + 255) / 256, 256>>>(dst, e, (const float2*)x,
                                            W1l, W1r, W2l, W2r, n);

    // CSR scan + fill (k_fill restores g_cnt zero-invariant)
    k_scan1<<<nb, 1024>>>(n);
    k_scan3<<<(n + 255) / 256, 256>>>(n, e, nb);
    k_fill <<<(e + 255) / 256, 256>>>(src, dst, e, n);

    int aggBlocks  = (n * 32 + 255) / 256;
    int gemmBlocks = (n + 127) / 128;

    // Layer 1: agg = mean(x[nbr]); h1 = relu([agg,x]@[W1l;W1r] + b1)
    k_agg_f<<<aggBlocks, 256>>>((const float4*)x, aggp, n);
    k_gemm_mma<true, true, false><<<gemmBlocks, 256, GEMM_SMEM>>>(
        aggp, xp, (const uint32_t*)pw1h, (const uint32_t*)pw1l,
        b1, h1p, nullptr, n);

    // Layer 2: agg = mean(h1[nbr]); h2 = [agg,h1]@[W2l;W2r] + b2, pooled inline
    k_agg_p<<<aggBlocks, 256>>>((const uint4*)h1p, aggp, n);
    k_gemm_mma<false, false, true><<<gemmBlocks, 256, GEMM_SMEM>>>(
        aggp, h1p, (const uint32_t*)pw2h, (const uint32_t*)pw2l,
        b2, nullptr, batch, n);

    // Global mean pool finalize (restores g_gsum/g_gcnt zero-invariants)
    k_final<<<1, 1024>>>(out);
}

// round 15
// speedup vs baseline: 1.0825x; 1.0825x over previous
#include <cuda_runtime.h>
#include <cuda_bf16.h>
#include <cstdint>

// ---------------------------------------------------------------------------
// GNN: 2-layer GraphSAGE (mean aggr) + global mean pool.
// GEMMs: mma.sync m16n8k16 bf16 (HMMA), split-bf16 3-term (AhBh+AhBl+AlBh),
// operands as {hi,lo} bf16 pairs (round-13 252us GEMM core, ROWU=40).
// This round: eliminate the g_xp pre-conversion — GEMM1 stages its A1 (=x)
// chunks by LDG.128 fp32 -> f2pair -> STS.128 (bitwise-identical pairs),
// removing 102 MB of cvt traffic. GEMM2 / agg kernels byte-identical to 252us.
// ---------------------------------------------------------------------------

#define MAXN 100000
#define MAXE 600000
#define NG   64
#define DD   128

// Scratch (device globals -- no runtime allocation allowed)
__device__ uint32_t g_aggp[MAXN * DD];   // aggregation output as pairs
__device__ uint32_t g_h1p [MAXN * DD];   // h1 (post-relu) as pairs
__device__ uint32_t g_wt1 [128 * 256];   // [n][k] pairs of stacked [W1l;W1r]
__device__ uint32_t g_wt2 [128 * 256];
__device__ int      g_cnt[MAXN];         // invariant: all-zero at entry
__device__ int      g_rowptr[MAXN + 1];
__device__ int      g_cursor[MAXN];
__device__ int      g_col[MAXE];
__device__ float    g_gsum[NG * DD];     // invariant: all-zero at entry
__device__ float    g_gcnt[NG];          // invariant: all-zero at entry
__device__ int      g_bsums[1024];

// ------------------------------------------------------------- bf16 pair ops
__device__ __forceinline__ uint32_t f2pair(float f) {
    __nv_bfloat16 h = __float2bfloat16(f);
    float hf = __bfloat162float(h);
    __nv_bfloat16 l = __float2bfloat16(f - hf);
    return (uint32_t)__bfloat16_as_ushort(h) |
           ((uint32_t)__bfloat16_as_ushort(l) << 16);
}
__device__ __forceinline__ float pair2f(uint32_t p) {
    float h = __uint_as_float(p << 16);
    float l = __uint_as_float(p & 0xffff0000u);
    return h + l;
}
__device__ __forceinline__ uint32_t prmt(uint32_t a, uint32_t b, uint32_t s) {
    uint32_t r;
    asm("prmt.b32 %0,%1,%2,%3;" : "=r"(r) : "r"(a), "r"(b), "r"(s));
    return r;
}

// --------------------------------------------------------------- PTX helpers
__device__ __forceinline__ uint32_t smem_u32(const void* p) {
    uint32_t a;
    asm("{ .reg .u64 t; cvta.to.shared.u64 t, %1; cvt.u32.u64 %0, t; }"
        : "=r"(a) : "l"(p));
    return a;
}
__device__ __forceinline__ void cpasync16(uint32_t smem, const void* gmem, int sz) {
    asm volatile("cp.async.ca.shared.global [%0], [%1], 16, %2;"
                 :: "r"(smem), "l"(gmem), "r"(sz));
}
__device__ __forceinline__ void cp_commit() {
    asm volatile("cp.async.commit_group;");
}
__device__ __forceinline__ void cp_wait1() {
    asm volatile("cp.async.wait_group 1;");
}
__device__ __forceinline__ void cp_wait0() {
    asm volatile("cp.async.wait_group 0;");
}

// mma.sync m16n8k16, bf16 x bf16 -> f32, accumulate in place
__device__ __forceinline__ void mma_bf16(float (&c)[4],
                                         uint32_t a0, uint32_t a1,
                                         uint32_t a2, uint32_t a3,
                                         uint32_t b0, uint32_t b1) {
    asm volatile(
        "mma.sync.aligned.m16n8k16.row.col.f32.bf16.bf16.f32 "
        "{%0,%1,%2,%3}, {%4,%5,%6,%7}, {%8,%9}, {%0,%1,%2,%3};"
        : "+f"(c[0]), "+f"(c[1]), "+f"(c[2]), "+f"(c[3])
        : "r"(a0), "r"(a1), "r"(a2), "r"(a3), "r"(b0), "r"(b1));
}

// ----------------- degree counts + weights->pairs (merged, independent work)
__global__ void k_cntcvt(const int* __restrict__ dst, int e,
                         const float* __restrict__ W1l, const float* __restrict__ W1r,
                         const float* __restrict__ W2l, const float* __restrict__ W2r) {
    int i = blockIdx.x * blockDim.x + threadIdx.x;
    if (i < e) atomicAdd(&g_cnt[dst[i]], 1);
    if (i < 2 * 128 * 256) {
        int which = i >> 15;
        int idx = i & 32767;
        int nn = idx >> 8;       // output col 0..127
        int k  = idx & 255;      // stacked K 0..255
        float v;
        if (which == 0) v = (k < 128) ? W1l[k * 128 + nn] : W1r[(k - 128) * 128 + nn];
        else            v = (k < 128) ? W2l[k * 128 + nn] : W2r[(k - 128) * 128 + nn];
        uint32_t* wt = which ? g_wt2 : g_wt1;
        wt[nn * 256 + k] = f2pair(v);
    }
}

// ---------------------------------------------- scan level 1 (per 1024 block)
__global__ void k_scan1(int n) {
    __shared__ int s[1024];
    int t = threadIdx.x;
    int i = blockIdx.x * 1024 + t;
    int v = (i < n) ? g_cnt[i] : 0;
    s[t] = v;
    __syncthreads();
    #pragma unroll
    for (int off = 1; off < 1024; off <<= 1) {
        int u = (t >= off) ? s[t - off] : 0;
        __syncthreads();
        s[t] += u;
        __syncthreads();
    }
    if (i < n) g_rowptr[i] = s[t];              // inclusive within block
    if (t == 1023) g_bsums[blockIdx.x] = s[1023];
}

// ------------- scan finalize: per-block smem prefix of bsums (folds scan2)
__global__ void k_scan3(int n, int e, int nb) {
    __shared__ int s[128];                      // nb <= 98 for MAXN=100000
    int t = threadIdx.x;
    if (t == 0) {
        int run = 0;
        for (int b = 0; b < nb; b++) { int v = g_bsums[b]; s[b] = run; run += v; }
    }
    __syncthreads();
    int i = blockIdx.x * blockDim.x + t;
    if (i < n) {
        int ex = s[i >> 10] + g_rowptr[i] - g_cnt[i];
        g_rowptr[i] = ex;
        g_cursor[i] = ex;
    }
    if (i == 0) g_rowptr[n] = e;
}

// ------------------------- CSR bucket fill (+ restore g_cnt zero-invariant)
__global__ void k_fill(const int* __restrict__ src, const int* __restrict__ dst,
                       int e, int n) {
    int i = blockIdx.x * blockDim.x + threadIdx.x;
    if (i < e) {
        int d = dst[i];
        int p = atomicAdd(&g_cursor[d], 1);
        g_col[p] = src[i];
    }
    if (i < n) g_cnt[i] = 0;
}

// -------------------------------------- mean aggregation, fp32 input (layer 1)
__global__ void k_agg_f(const float4* __restrict__ xin, uint32_t* __restrict__ outp, int n) {
    int gt = blockIdx.x * blockDim.x + threadIdx.x;
    int node = gt >> 5;
    int lane = gt & 31;
    if (node >= n) return;
    int beg = g_rowptr[node];
    int end = g_rowptr[node + 1];
    float4 acc = make_float4(0.f, 0.f, 0.f, 0.f);
    for (int e = beg; e < end; e++) {
        int j = g_col[e];
        float4 v = __ldg(&xin[j * 32 + lane]);
        acc.x += v.x; acc.y += v.y; acc.z += v.z; acc.w += v.w;
    }
    int deg = end - beg;
    float s = 1.0f / (float)(deg > 0 ? deg : 1);
    uint4 o;
    o.x = f2pair(acc.x * s); o.y = f2pair(acc.y * s);
    o.z = f2pair(acc.z * s); o.w = f2pair(acc.w * s);
    *(uint4*)&outp[node * 128 + lane * 4] = o;
}

// -------------------------------------- mean aggregation, pair input (layer 2)
__global__ void k_agg_p(const uint4* __restrict__ inp, uint32_t* __restrict__ outp, int n) {
    int gt = blockIdx.x * blockDim.x + threadIdx.x;
    int node = gt >> 5;
    int lane = gt & 31;
    if (node >= n) return;
    int beg = g_rowptr[node];
    int end = g_rowptr[node + 1];
    float4 acc = make_float4(0.f, 0.f, 0.f, 0.f);
    for (int e = beg; e < end; e++) {
        int j = g_col[e];
        uint4 v = __ldg(&inp[j * 32 + lane]);
        acc.x += pair2f(v.x); acc.y += pair2f(v.y);
        acc.z += pair2f(v.z); acc.w += pair2f(v.w);
    }
    int deg = end - beg;
    float s = 1.0f / (float)(deg > 0 ? deg : 1);
    uint4 o;
    o.x = f2pair(acc.x * s); o.y = f2pair(acc.y * s);
    o.z = f2pair(acc.z * s); o.w = f2pair(acc.w * s);
    *(uint4*)&outp[node * 128 + lane * 4] = o;
}

// ------------------------------------------------- split-bf16 HMMA dual GEMM
// C[M=128/blk, N=128] = [A0 | A1](K=256 pairs) @ Bw^T + bias
// 3 MMA terms: AhBh + AhBl + AlBh. K chunks of 32 pairs, cp.async 2-stage.
// smem tile rows padded to 40 uint32 (160B): conflict-free main-loop LDS.64.
// CVT_A1: A1 is fp32 (= x); loader LDGs fp32, f2pair-converts, STS pairs
// (bitwise identical to pre-converted path). Else A1 is a pair array.
// POOL epilogue (GEMM2): tile -> smem, per-block segment sums, few atomics.
#define ROWU 40                            // uint32 per smem row
#define STAGE_BYTES (2 * 128 * ROWU * 4)   // A tile + B tile per stage (40960)
#define TILE_STRIDE 132                    // fp32 pool-tile row stride

template <bool RELU, bool PAIR_OUT, bool POOL, bool CVT_A1>
__global__ void __launch_bounds__(256, 2)
k_gemm_mma(const uint32_t* __restrict__ A0, const void* __restrict__ A1,
           const uint32_t* __restrict__ Bw, const float* __restrict__ bias,
           void* __restrict__ Cout, const int* __restrict__ batch, int n) {
    extern __shared__ __align__(16) unsigned char smraw[];
    uint32_t sbase = smem_u32(smraw);

    int tid = threadIdx.x;
    int wid = tid >> 5;
    int lid = tid & 31;
    int g = lid >> 2;                 // group 0..7
    int t = lid & 3;                  // thread-in-group
    int rowBase = blockIdx.x * 128;
    int rowWarp = (wid >> 1) * 32;    // warp tile: 32 rows x 64 cols
    int colWarp = (wid & 1) * 64;

    float acc[2][8][4];
    #pragma unroll
    for (int rt = 0; rt < 2; rt++)
        #pragma unroll
        for (int ct = 0; ct < 8; ct++)
            #pragma unroll
            for (int q = 0; q < 4; q++) acc[rt][ct][q] = 0.0f;

    // ---- chunk loader (k-chunk c -> stage st) -------------------------------
    auto load_chunk = [&](int c, int st) {
        int ko = (c & 3) * 32;            // pair offset within source
        int kb = c * 32;                  // pair offset within stacked K
        uint32_t sA = sbase + st * STAGE_BYTES;
        uint32_t sB = sA + 128 * ROWU * 4;
        if (CVT_A1 && c >= 4) {
            // A1 = fp32 x: LDG.128 -> f2pair x4 -> STS.128 (same smem layout)
            const float4* A1f = (const float4*)A1;
            #pragma unroll
            for (int j = 0; j < 4; j++) {
                int idx = tid + j * 256;
                int r = idx >> 3, seg = idx & 7;
                int gr = rowBase + r;
                uint4 o = make_uint4(0u, 0u, 0u, 0u);
                if (gr < n) {
                    float4 v = __ldg(&A1f[(size_t)gr * 32 + (c & 3) * 8 + seg]);
                    o.x = f2pair(v.x); o.y = f2pair(v.y);
                    o.z = f2pair(v.z); o.w = f2pair(v.w);
                }
                *(uint4*)(smraw + st * STAGE_BYTES + r * (ROWU * 4) + seg * 16) = o;
            }
        } else {
            const uint32_t* Asrc = (c < 4) ? A0 : (const uint32_t*)A1;
            #pragma unroll
            for (int j = 0; j < 4; j++) {     // A: 128 rows x 32 pairs
                int idx = tid + j * 256;
                int r = idx >> 3, seg = idx & 7;
                int gr = rowBase + r;
                int sz = (gr < n) ? 16 : 0;
                int grc = (gr < n) ? gr : (n - 1);
                cpasync16(sA + r * (ROWU * 4) + seg * 16,
                          Asrc + (size_t)grc * 128 + ko + seg * 4, sz);
            }
        }
        #pragma unroll
        for (int j = 0; j < 4; j++) {     // B: 128 n-rows x 32 pairs
            int idx = tid + j * 256;
            int r = idx >> 3, seg = idx & 7;
            cpasync16(sB + r * (ROWU * 4) + seg * 16,
                      Bw + r * 256 + kb + seg * 4, 16);
        }
        cp_commit();
    };

    load_chunk(0, 0);

    for (int c = 0; c < 8; c++) {
        if (c < 7) { load_chunk(c + 1, (c + 1) & 1); cp_wait1(); }
        else       { cp_wait0(); }
        __syncthreads();

        const uint32_t* sA = (const uint32_t*)(smraw + (c & 1) * STAGE_BYTES);
        const uint32_t* sB = sA + 128 * ROWU;

        #pragma unroll
        for (int kk = 0; kk < 32; kk += 16) {
            uint32_t Ah[2][4], Al[2][4];
            #pragma unroll
            for (int rt = 0; rt < 2; rt++) {
                const uint32_t* p0 = sA + (rowWarp + rt * 16 + g) * ROWU + kk + 2 * t;
                const uint32_t* p1 = p0 + 8 * ROWU;
                uint2 q;
                q = *(const uint2*)p0;
                Ah[rt][0] = prmt(q.x, q.y, 0x5410); Al[rt][0] = prmt(q.x, q.y, 0x7632);
                q = *(const uint2*)p1;
                Ah[rt][1] = prmt(q.x, q.y, 0x5410); Al[rt][1] = prmt(q.x, q.y, 0x7632);
                q = *(const uint2*)(p0 + 8);
                Ah[rt][2] = prmt(q.x, q.y, 0x5410); Al[rt][2] = prmt(q.x, q.y, 0x7632);
                q = *(const uint2*)(p1 + 8);
                Ah[rt][3] = prmt(q.x, q.y, 0x5410); Al[rt][3] = prmt(q.x, q.y, 0x7632);
            }
            #pragma unroll
            for (int ct = 0; ct < 8; ct++) {
                const uint32_t* pb = sB + (colWarp + ct * 8 + g) * ROWU + kk + 2 * t;
                uint2 q0 = *(const uint2*)pb;
                uint2 q1 = *(const uint2*)(pb + 8);
                uint32_t Bh0 = prmt(q0.x, q0.y, 0x5410), Bl0 = prmt(q0.x, q0.y, 0x7632);
                uint32_t Bh1 = prmt(q1.x, q1.y, 0x5410), Bl1 = prmt(q1.x, q1.y, 0x7632);
                #pragma unroll
                for (int rt = 0; rt < 2; rt++) {
                    mma_bf16(acc[rt][ct], Ah[rt][0], Ah[rt][1], Ah[rt][2], Ah[rt][3], Bh0, Bh1);
                    mma_bf16(acc[rt][ct], Ah[rt][0], Ah[rt][1], Ah[rt][2], Ah[rt][3], Bl0, Bl1);
                    mma_bf16(acc[rt][ct], Al[rt][0], Al[rt][1], Al[rt][2], Al[rt][3], Bh0, Bh1);
                }
            }
        }
        __syncthreads();
    }

    // ---- epilogue -----------------------------------------------------------
    float bc0[8], bc1[8];
    #pragma unroll
    for (int ct = 0; ct < 8; ct++) {
        int col = colWarp + ct * 8 + 2 * t;
        bc0[ct] = __ldg(&bias[col]);
        bc1[ct] = __ldg(&bias[col + 1]);
    }

    if (POOL) {
        // Fused global-mean-pool: stash tile in smem (stage buffers are dead
        // after the last __syncthreads), segment-sum columns by sorted batch.
        float* tile = (float*)smraw;                          // 128 x TILE_STRIDE
        int* sbatch = (int*)(smraw + 128 * TILE_STRIDE * 4);  // 128 ids
        #pragma unroll
        for (int rt = 0; rt < 2; rt++) {
            #pragma unroll
            for (int half = 0; half < 2; half++) {
                int lrow = rowWarp + rt * 16 + half * 8 + g;
                #pragma unroll
                for (int ct = 0; ct < 8; ct++) {
                    int col = colWarp + ct * 8 + 2 * t;
                    float v0 = acc[rt][ct][half * 2 + 0] + bc0[ct];
                    float v1 = acc[rt][ct][half * 2 + 1] + bc1[ct];
                    if (RELU) { v0 = fmaxf(v0, 0.f); v1 = fmaxf(v1, 0.f); }
                    float2 o; o.x = v0; o.y = v1;
                    *(float2*)&tile[lrow * TILE_STRIDE + col] = o;
                }
            }
        }
        if (tid < 128) {
            int gr = rowBase + tid;
            sbatch[tid] = (gr < n) ? __ldg(&batch[gr]) : -1;
        }
        __syncthreads();
        if (tid < 128) {
            int col = tid;
            float pacc = 0.0f;
            int cur = sbatch[0];
            int cnt = 0;
            for (int r = 0; r < 128; r++) {
                int b = sbatch[r];
                if (b != cur) {
                    if (cur >= 0) {
                        atomicAdd(&g_gsum[cur * DD + col], pacc);
                        if (col == 0) atomicAdd(&g_gcnt[cur], (float)cnt);
                    }
                    pacc = 0.0f; cnt = 0; cur = b;
                }
                if (b >= 0) { pacc += tile[r * TILE_STRIDE + col]; cnt++; }
            }
            if (cur >= 0) {
                atomicAdd(&g_gsum[cur * DD + col], pacc);
                if (col == 0) atomicAdd(&g_gcnt[cur], (float)cnt);
            }
        }
    } else {
        #pragma unroll
        for (int rt = 0; rt < 2; rt++) {
            #pragma unroll
            for (int half = 0; half < 2; half++) {
                int grow = rowBase + rowWarp + rt * 16 + half * 8 + g;
                if (grow >= n) continue;
                #pragma unroll
                for (int ct = 0; ct < 8; ct++) {
                    int col = colWarp + ct * 8 + 2 * t;
                    float v0 = acc[rt][ct][half * 2 + 0] + bc0[ct];
                    float v1 = acc[rt][ct][half * 2 + 1] + bc1[ct];
                    if (RELU) { v0 = fmaxf(v0, 0.f); v1 = fmaxf(v1, 0.f); }
                    if (PAIR_OUT) {
                        uint2 o; o.x = f2pair(v0); o.y = f2pair(v1);
                        *(uint2*)&((uint32_t*)Cout)[(size_t)grow * 128 + col] = o;
                    } else {
                        float2 o; o.x = v0; o.y = v1;
                        *(float2*)&((float*)Cout)[(size_t)grow * 128 + col] = o;
                    }
                }
            }
        }
    }
}

// -------------- final output (single block; restores zero-invariants)
__global__ void k_final(float* __restrict__ out) {
    __shared__ float sc[NG];
    int t = threadIdx.x;
    if (t < NG) sc[t] = g_gcnt[t];
    __syncthreads();
    for (int i = t; i < NG * DD; i += 1024) {
        out[i] = g_gsum[i] / fmaxf(sc[i >> 7], 1.0f);
        g_gsum[i] = 0.0f;
    }
    if (t < NG) g_gcnt[t] = 0.0f;
}

// ---------------------------------------------------------------------------
extern "C" void kernel_launch(void* const* d_in, const int* in_sizes, int n_in,
                              void* d_out, int out_size) {
    (void)n_in; (void)out_size;
    const float* x     = (const float*)d_in[0];
    const int*   ei    = (const int*)  d_in[1];
    const int*   batch = (const int*)  d_in[2];
    const float* W1l   = (const float*)d_in[3];
    const float* b1    = (const float*)d_in[4];
    const float* W1r   = (const float*)d_in[5];
    const float* W2l   = (const float*)d_in[6];
    const float* b2    = (const float*)d_in[7];
    const float* W2r   = (const float*)d_in[8];
    float*       out   = (float*)d_out;

    int n = in_sizes[0] / 128;   // nodes
    int e = in_sizes[1] / 2;     // edges
    const int* src = ei;         // edge_index[0]
    const int* dst = ei + e;     // edge_index[1]

    void *p_aggp, *p_h1p, *p_wt1, *p_wt2;
    cudaGetSymbolAddress(&p_aggp, g_aggp);
    cudaGetSymbolAddress(&p_h1p,  g_h1p);
    cudaGetSymbolAddress(&p_wt1,  g_wt1);
    cudaGetSymbolAddress(&p_wt2,  g_wt2);
    uint32_t* aggp = (uint32_t*)p_aggp;
    uint32_t* h1p  = (uint32_t*)p_h1p;
    uint32_t* wt1  = (uint32_t*)p_wt1;
    uint32_t* wt2  = (uint32_t*)p_wt2;

    const int GEMM_SMEM = 2 * STAGE_BYTES;   // 81920 (covers pool tile 68096)
    cudaFuncSetAttribute(k_gemm_mma<true, true, false, true>,
                         cudaFuncAttributeMaxDynamicSharedMemorySize, GEMM_SMEM);
    cudaFuncSetAttribute(k_gemm_mma<false, false, true, false>,
                         cudaFuncAttributeMaxDynamicSharedMemorySize, GEMM_SMEM);

    int nb = (n + 1023) / 1024;

    // Counts + weight conversion in one kernel (g_cnt arrives zeroed)
    int cntTot = (2 * 128 * 256 > e) ? 2 * 128 * 256 : e;
    k_cntcvt<<<(cntTot + 255) / 256, 256>>>(dst, e, W1l, W1r, W2l, W2r);

    // CSR scan + fill (k_fill restores g_cnt zero-invariant)
    k_scan1<<<nb, 1024>>>(n);
    k_scan3<<<(n + 255) / 256, 256>>>(n, e, nb);
    k_fill <<<(e + 255) / 256, 256>>>(src, dst, e, n);

    int aggBlocks  = (n * 32 + 255) / 256;
    int gemmBlocks = (n + 127) / 128;

    // Layer 1: agg = mean(x[nbr]); h1 = relu([agg,x]@[W1l;W1r] + b1)
    // A1 = x (fp32), converted to pairs on-the-fly in the GEMM loader.
    k_agg_f<<<aggBlocks, 256>>>((const float4*)x, aggp, n);
    k_gemm_mma<true, true, false, true><<<gemmBlocks, 256, GEMM_SMEM>>>(
        aggp, x, wt1, b1, h1p, nullptr, n);

    // Layer 2: agg = mean(h1[nbr]); h2 = [agg,h1]@[W2l;W2r] + b2, pooled inline
    k_agg_p<<<aggBlocks, 256>>>((const uint4*)h1p, aggp, n);
    k_gemm_mma<false, false, true, false><<<gemmBlocks, 256, GEMM_SMEM>>>(
        aggp, h1p, wt2, b2, nullptr, batch, n);

    // Global mean pool finalize (restores g_gsum/g_gcnt zero-invariants)
    k_final<<<1, 1024>>>(out);
}